// round 1
// baseline (speedup 1.0000x reference)
#include <cuda_runtime.h>
#include <cstdint>

// Problem constants
#define NB 512
#define ND 256
#define NC 10

// Weights in constant memory (filled by async D2D copies each launch; capturable)
__constant__ float c_w1[NC];
__constant__ float c_b1[NC];
__constant__ float c_w2[NC * 9];   // [c][kh][kw]
__constant__ float c_b2;

// Scratch (static device allocations are allowed)
__device__ float g_rs[NB * ND];
__device__ float g_cs[NB * ND];
__device__ float g_v [NB * ND];
__device__ float g_part[256 * 4];

// ---------------------------------------------------------------------------
// Kernel A: per-batch row sums and column sums of x  (pure streaming, HBM-bound)
// grid = 512 (one block per batch), block = 256 (8 warps)
// warp w handles rows [32w, 32w+32); lane l covers columns 8l..8l+7
// ---------------------------------------------------------------------------
__global__ void __launch_bounds__(256) ksums(const float* __restrict__ x) {
    const int b = blockIdx.x;
    const int t = threadIdx.x;
    const int w = t >> 5;
    const int l = t & 31;

    __shared__ float scs[8 * 256];

    const float4* __restrict__ xb =
        reinterpret_cast<const float4*>(x + (size_t)b * (ND * ND));

    float ca[8];
#pragma unroll
    for (int k = 0; k < 8; ++k) ca[k] = 0.f;

    const int i0 = 32 * w;
    for (int i = i0; i < i0 + 32; ++i) {
        float4 v0 = xb[i * 64 + 2 * l];
        float4 v1 = xb[i * 64 + 2 * l + 1];
        ca[0] += v0.x; ca[1] += v0.y; ca[2] += v0.z; ca[3] += v0.w;
        ca[4] += v1.x; ca[5] += v1.y; ca[6] += v1.z; ca[7] += v1.w;
        float rsum = (v0.x + v0.y) + (v0.z + v0.w) + (v1.x + v1.y) + (v1.z + v1.w);
#pragma unroll
        for (int o = 16; o; o >>= 1) rsum += __shfl_xor_sync(0xffffffffu, rsum, o);
        if (l == 0) g_rs[b * ND + i] = rsum;
    }

#pragma unroll
    for (int k = 0; k < 8; ++k) scs[w * 256 + 8 * l + k] = ca[k];
    __syncthreads();

    float c = 0.f;
#pragma unroll
    for (int ww = 0; ww < 8; ++ww) c += scs[ww * 256 + t];
    g_cs[b * ND + t] = c;
}

// ---------------------------------------------------------------------------
// Kernel B: band conv + row/col sums of y, writing v[b, :]
// grid = 512 (one block per batch), block = 256 (thread j = column j)
//
// h[c,p,q] = relu(w1[c]*(rs[p]+cs[q]) + b1[c]) * [q <= p]
// y[i,j]   = relu(b2 + sum_{c,dr,dc} w2[c,dr+1,dc+1] h[c,i+dr,j+dc])
// For j >= i+3 all taps are masked -> y = c0 = relu(b2): handled analytically.
// Rolling pipeline: a_d[p] = sum_{c,dc} w2[c,d,dc] h[c,p,j+dc];
//   y[i] = a_0[i-1] + a_1[i] + a_2[i+1]
// ---------------------------------------------------------------------------
__device__ __forceinline__ void tap10(float t, int dcc, float& a0, float& a1, float& a2) {
#pragma unroll
    for (int c = 0; c < NC; ++c) {
        float g = fmaxf(fmaf(c_w1[c], t, c_b1[c]), 0.f);
        a0 = fmaf(c_w2[c * 9 + 0 + dcc], g, a0);
        a1 = fmaf(c_w2[c * 9 + 3 + dcc], g, a1);
        a2 = fmaf(c_w2[c * 9 + 6 + dcc], g, a2);
    }
}

__global__ void __launch_bounds__(256) kband() {
    const int b = blockIdx.x;
    const int j = threadIdx.x;
    const int w = j >> 5;

    __shared__ float srs[256];
    __shared__ float srow8[8 * 256];   // per-warp row-sum partials (deterministic)

    srs[j] = g_rs[b * ND + j];
#pragma unroll
    for (int ww = 0; ww < 8; ++ww) srow8[ww * 256 + j] = 0.f;

    const bool vm1 = (j >= 1);
    const bool vp1 = (j <= 254);
    const float csm1 = vm1 ? g_cs[b * ND + j - 1] : 0.f;
    const float cs0  = g_cs[b * ND + j];
    const float csp1 = vp1 ? g_cs[b * ND + j + 1] : 0.f;
    __syncthreads();

    const float b2v = c_b2;
    const float c0  = fmaxf(b2v, 0.f);

    float pend1 = 0.f, a0_last = 0.f, colacc = 0.f;
    const int pstart = (32 * w >= 3) ? (32 * w - 3) : 0;

    for (int p = pstart; p < 256; ++p) {
        const float rsp = srs[p];
        float a0 = 0.f, a1 = 0.f, a2 = 0.f;

        if (vm1 && (j - 1) <= p) tap10(rsp + csm1, 0, a0, a1, a2);
        if (j <= p)              tap10(rsp + cs0,  1, a0, a1, a2);
        if (vp1 && (j + 1) <= p) tap10(rsp + csp1, 2, a0, a1, a2);

        if (p >= 1) {
            float y  = fmaxf(pend1 + a2 + b2v, 0.f);
            float yc = (j <= p + 1) ? y : 0.f;   // band predicate: i = p-1 >= j-2
            colacc += yc;
            float rsum = yc;
#pragma unroll
            for (int o = 16; o; o >>= 1) rsum += __shfl_xor_sync(0xffffffffu, rsum, o);
            if ((j & 31) == 0) srow8[w * 256 + (p - 1)] += rsum;
        }
        pend1   = a1 + a0_last;
        a0_last = a0;
    }
    // epilogue row i = 255 (phantom p = 256 contributes a = 0)
    {
        float y = fmaxf(pend1 + b2v, 0.f);
        colacc += y;
        float rsum = y;
#pragma unroll
        for (int o = 16; o; o >>= 1) rsum += __shfl_xor_sync(0xffffffffu, rsum, o);
        if ((j & 31) == 0) srow8[w * 256 + 255] += rsum;
    }
    __syncthreads();

    float rowtot = 0.f;
#pragma unroll
    for (int ww = 0; ww < 8; ++ww) rowtot += srow8[ww * 256 + j];

    // analytic constant-region corrections
    const float rowc = c0 * (float)((253 - j) > 0 ? (253 - j) : 0);
    const float colc = c0 * (float)((j - 2)  > 0 ? (j - 2)  : 0);

    g_v[b * ND + j] = rowtot + rowc + colacc + colc;
}

// ---------------------------------------------------------------------------
// Kernel C1: partial dot products fc1_w[k,:] . v   (k = 0..3)
// grid = 256 blocks x 256 threads, each block covers 512 elements
// ---------------------------------------------------------------------------
__global__ void __launch_bounds__(256) kfc1(const float* __restrict__ fc1w) {
    __shared__ float red[8 * 4];
    const int t = threadIdx.x;
    const int base = blockIdx.x * 512;

    float p0 = 0.f, p1 = 0.f, p2 = 0.f, p3 = 0.f;
#pragma unroll
    for (int r = 0; r < 2; ++r) {
        int n = base + t + r * 256;
        float f = g_v[n];
        p0 = fmaf(fc1w[n],               f, p0);
        p1 = fmaf(fc1w[131072 + n],      f, p1);
        p2 = fmaf(fc1w[262144 + n],      f, p2);
        p3 = fmaf(fc1w[393216 + n],      f, p3);
    }
#pragma unroll
    for (int o = 16; o; o >>= 1) {
        p0 += __shfl_xor_sync(0xffffffffu, p0, o);
        p1 += __shfl_xor_sync(0xffffffffu, p1, o);
        p2 += __shfl_xor_sync(0xffffffffu, p2, o);
        p3 += __shfl_xor_sync(0xffffffffu, p3, o);
    }
    if ((t & 31) == 0) {
        int w = t >> 5;
        red[w * 4 + 0] = p0; red[w * 4 + 1] = p1;
        red[w * 4 + 2] = p2; red[w * 4 + 3] = p3;
    }
    __syncthreads();
    if (t < 4) {
        float s = 0.f;
#pragma unroll
        for (int w = 0; w < 8; ++w) s += red[w * 4 + t];
        g_part[blockIdx.x * 4 + t] = s;
    }
}

// ---------------------------------------------------------------------------
// Kernel C2: final reduction + fc2   (1 warp)
// ---------------------------------------------------------------------------
__global__ void kfc2(const float* __restrict__ fc1b,
                     const float* __restrict__ fc2w,
                     const float* __restrict__ fc2b,
                     float* __restrict__ out) {
    const int l = threadIdx.x;
    float s0 = 0.f, s1 = 0.f, s2 = 0.f, s3 = 0.f;
    for (int i = l; i < 256; i += 32) {
        s0 += g_part[i * 4 + 0];
        s1 += g_part[i * 4 + 1];
        s2 += g_part[i * 4 + 2];
        s3 += g_part[i * 4 + 3];
    }
#pragma unroll
    for (int o = 16; o; o >>= 1) {
        s0 += __shfl_xor_sync(0xffffffffu, s0, o);
        s1 += __shfl_xor_sync(0xffffffffu, s1, o);
        s2 += __shfl_xor_sync(0xffffffffu, s2, o);
        s3 += __shfl_xor_sync(0xffffffffu, s3, o);
    }
    if (l == 0) {
        float h0 = fmaxf(s0 + fc1b[0], 0.f);
        float h1 = fmaxf(s1 + fc1b[1], 0.f);
        float h2 = fmaxf(s2 + fc1b[2], 0.f);
        float h3 = fmaxf(s3 + fc1b[3], 0.f);
        out[0] = fc2w[0] * h0 + fc2w[1] * h1 + fc2w[2] * h2 + fc2w[3] * h3 + fc2b[0];
        out[1] = fc2w[4] * h0 + fc2w[5] * h1 + fc2w[6] * h2 + fc2w[7] * h3 + fc2b[1];
    }
}

// ---------------------------------------------------------------------------
extern "C" void kernel_launch(void* const* d_in, const int* in_sizes, int n_in,
                              void* d_out, int out_size) {
    const float* x     = (const float*)d_in[0];
    const float* fc1w  = (const float*)d_in[5];
    const float* fc1b  = (const float*)d_in[6];
    const float* fc2w  = (const float*)d_in[7];
    const float* fc2b  = (const float*)d_in[8];

    cudaMemcpyToSymbolAsync(c_w1, d_in[1], NC * sizeof(float), 0, cudaMemcpyDeviceToDevice, 0);
    cudaMemcpyToSymbolAsync(c_b1, d_in[2], NC * sizeof(float), 0, cudaMemcpyDeviceToDevice, 0);
    cudaMemcpyToSymbolAsync(c_w2, d_in[3], NC * 9 * sizeof(float), 0, cudaMemcpyDeviceToDevice, 0);
    cudaMemcpyToSymbolAsync(c_b2, d_in[4], sizeof(float), 0, cudaMemcpyDeviceToDevice, 0);

    ksums<<<NB, 256>>>(x);
    kband<<<NB, 256>>>();
    kfc1 <<<256, 256>>>(fc1w);
    kfc2 <<<1, 32>>>(fc1b, fc2w, fc2b, (float*)d_out);
}

// round 2
// speedup vs baseline: 1.1444x; 1.1444x over previous
#include <cuda_runtime.h>
#include <cstdint>

#define NB 512
#define ND 256
#define NC 10

// ---------------------------------------------------------------------------
// packed fp32x2 helpers (Blackwell packed-fp32 pipe; one instr = 2 fp32 lanes)
// ---------------------------------------------------------------------------
typedef unsigned long long ps_t;

__device__ __forceinline__ ps_t pk2(float lo, float hi) {
    ps_t o; asm("mov.b64 %0,{%1,%2};" : "=l"(o) : "f"(lo), "f"(hi)); return o;
}
__device__ __forceinline__ void up2(ps_t a, float& lo, float& hi) {
    asm("mov.b64 {%0,%1},%2;" : "=f"(lo), "=f"(hi) : "l"(a));
}
__device__ __forceinline__ ps_t fma2(ps_t a, ps_t b, ps_t c) {
    ps_t d; asm("fma.rn.f32x2 %0,%1,%2,%3;" : "=l"(d) : "l"(a), "l"(b), "l"(c)); return d;
}
__device__ __forceinline__ ps_t add2(ps_t a, ps_t b) {
    ps_t d; asm("add.rn.f32x2 %0,%1,%2;" : "=l"(d) : "l"(a), "l"(b)); return d;
}
__device__ __forceinline__ ps_t relu2(ps_t a) {
    float l, h; up2(a, l, h);
    return pk2(fmaxf(l, 0.f), fmaxf(h, 0.f));
}

// packed weights: [0:10) w1, [10:20) b1, [20:110) w2[c*9 + kh*3 + kw], [110] b2
__constant__ ps_t c_pack[111];
__device__ ps_t g_pack[111];
__device__ float g_part[256 * 4];

// ---------------------------------------------------------------------------
// prep: duplicate scalar weights into both fp32x2 lanes
// ---------------------------------------------------------------------------
__global__ void kprep(const float* __restrict__ w1, const float* __restrict__ b1,
                      const float* __restrict__ w2, const float* __restrict__ b2) {
    int t = threadIdx.x;
    if (t < 10) { g_pack[t] = pk2(w1[t], w1[t]); g_pack[10 + t] = pk2(b1[t], b1[t]); }
    if (t < 90) g_pack[20 + t] = pk2(w2[t], w2[t]);
    if (t == 0) g_pack[110] = pk2(b2[0], b2[0]);
}

// ---------------------------------------------------------------------------
// tap: 10-channel generate + 3-row accumulate for one conv column e (0..2)
// per call: 10 fma2 (gen) + relu + 30 fma2 (acc); weights via LDCU/URs
// ---------------------------------------------------------------------------
__device__ __forceinline__ void tap2(ps_t t2, int e, ps_t& A0, ps_t& A1, ps_t& A2) {
#pragma unroll
    for (int c = 0; c < NC; ++c) {
        ps_t g = relu2(fma2(c_pack[c], t2, c_pack[10 + c]));
        A0 = fma2(c_pack[20 + c * 9 + 0 + e], g, A0);
        A1 = fma2(c_pack[20 + c * 9 + 3 + e], g, A1);
        A2 = fma2(c_pack[20 + c * 9 + 6 + e], g, A2);
    }
}

// ---------------------------------------------------------------------------
// main fused kernel: one block = batch pair (2*bi, 2*bi+1), 256 threads.
// Phase 1: rs/cs of both batches (streaming).
// Phase 2: band conv + row/col sums of y, packed over the 2 batches.
// Epilogue: v -> fc1 partial dot products.
// Warp w -> column range r = (w<4) ? w : 11-w  (balances SMSP load: pairs
// {0,7},{1,6},{2,5},{3,4} each sum to 294 p-iterations).
// ---------------------------------------------------------------------------
__global__ void __launch_bounds__(256) kmain(const float* __restrict__ x,
                                             const float* __restrict__ fc1w) {
    const int bi = blockIdx.x;
    const int t = threadIdx.x;
    const int w = t >> 5;
    const int lane = t & 31;

    __shared__ ps_t srs2[ND];
    __shared__ ps_t scs2[ND];
    __shared__ ps_t srow2[8][ND];   // per-warp packed row sums; phase-1 scratch
    __shared__ float sred[8][4];

    float* scratch = (float*)&srow2[0][0];   // 8*256 floats

    // ---------------- phase 1: rs / cs for both batches ----------------
#pragma unroll
    for (int hb = 0; hb < 2; ++hb) {
        const int b = 2 * bi + hb;
        const float4* __restrict__ xb =
            reinterpret_cast<const float4*>(x + (size_t)b * (ND * ND));
        float ca[8];
#pragma unroll
        for (int k = 0; k < 8; ++k) ca[k] = 0.f;

        const int i0 = 32 * w;
        for (int i = i0; i < i0 + 32; ++i) {
            float4 v0 = xb[i * 64 + 2 * lane];
            float4 v1 = xb[i * 64 + 2 * lane + 1];
            ca[0] += v0.x; ca[1] += v0.y; ca[2] += v0.z; ca[3] += v0.w;
            ca[4] += v1.x; ca[5] += v1.y; ca[6] += v1.z; ca[7] += v1.w;
            float rsum = (v0.x + v0.y) + (v0.z + v0.w) + (v1.x + v1.y) + (v1.z + v1.w);
#pragma unroll
            for (int o = 16; o; o >>= 1) rsum += __shfl_xor_sync(0xffffffffu, rsum, o);
            if (lane == 0) ((float*)&srs2[i])[hb] = rsum;
        }
#pragma unroll
        for (int k = 0; k < 8; ++k) scratch[w * 256 + 8 * lane + k] = ca[k];
        __syncthreads();
        {
            float c = 0.f;
#pragma unroll
            for (int ww = 0; ww < 8; ++ww) c += scratch[ww * 256 + t];
            ((float*)&scs2[t])[hb] = c;
        }
        __syncthreads();
    }

    // zero per-warp row-sum buffer (scratch reads are done)
#pragma unroll
    for (int k = 0; k < 8; ++k) srow2[k][t] = 0ULL;
    __syncthreads();

    // ---------------- phase 2: band conv ----------------
    const int r = (w < 4) ? w : 11 - w;
    const int j = 32 * r + lane;
    const bool vm1 = (j >= 1);
    const bool vp1 = (j <= 254);
    const ps_t csm = vm1 ? scs2[j - 1] : 0ULL;
    const ps_t cs0 = scs2[j];
    const ps_t csp = vp1 ? scs2[j + 1] : 0ULL;

    const ps_t b2v = c_pack[110];
    float b2f, b2d; up2(b2v, b2f, b2d);
    const float c0 = fmaxf(b2f, 0.f);

    ps_t pend1 = 0ULL, a0last = 0ULL, colacc = 0ULL;
    const int pstart = (32 * r >= 3) ? (32 * r - 3) : 0;

#pragma unroll 2
    for (int p = pstart; p < ND; ++p) {
        const ps_t rsp = srs2[p];
        ps_t A0 = 0ULL, A1 = 0ULL, A2 = 0ULL;

        if (vm1 && (j - 1) <= p) tap2(add2(rsp, csm), 0, A0, A1, A2);
        if ((j) <= p)            tap2(add2(rsp, cs0), 1, A0, A1, A2);
        if (vp1 && (j + 1) <= p) tap2(add2(rsp, csp), 2, A0, A1, A2);

        if (p >= 1) {
            ps_t y = relu2(add2(add2(pend1, A2), b2v));
            ps_t yc = (j <= p + 1) ? y : 0ULL;     // band mask: i = p-1 >= j-2
            colacc = add2(colacc, yc);
            ps_t rsum = yc;
#pragma unroll
            for (int o = 16; o; o >>= 1)
                rsum = add2(rsum, __shfl_xor_sync(0xffffffffu, rsum, o));
            if (lane == 0) srow2[r][p - 1] = rsum;
        }
        pend1 = add2(A1, a0last);
        a0last = A0;
    }
    // epilogue: row i = 255 (phantom p = 256 contributes nothing)
    {
        ps_t y = relu2(add2(pend1, b2v));
        colacc = add2(colacc, y);
        ps_t rsum = y;
#pragma unroll
        for (int o = 16; o; o >>= 1)
            rsum = add2(rsum, __shfl_xor_sync(0xffffffffu, rsum, o));
        if (lane == 0) srow2[r][ND - 1] = rsum;
    }
    __syncthreads();

    ps_t rowtot = 0ULL;
#pragma unroll
    for (int k = 0; k < 8; ++k) rowtot = add2(rowtot, srow2[k][j]);

    // analytic constant-region corrections
    const int rn = (253 - j) > 0 ? (253 - j) : 0;
    const int cn = (j - 2) > 0 ? (j - 2) : 0;
    const float corr = c0 * (float)(rn + cn);

    const ps_t v2 = add2(add2(rowtot, colacc), pk2(corr, corr));
    float v0f, v1f; up2(v2, v0f, v1f);

    // ---------------- epilogue: fc1 partial dots ----------------
    const int b0 = 2 * bi;
    float pk4[4];
#pragma unroll
    for (int k = 0; k < 4; ++k) {
        const float* wrow = fc1w + (size_t)k * 131072 + b0 * 256 + j;
        pk4[k] = wrow[0] * v0f + wrow[256] * v1f;
    }
#pragma unroll
    for (int o = 16; o; o >>= 1) {
#pragma unroll
        for (int k = 0; k < 4; ++k)
            pk4[k] += __shfl_xor_sync(0xffffffffu, pk4[k], o);
    }
    if (lane == 0) {
#pragma unroll
        for (int k = 0; k < 4; ++k) sred[w][k] = pk4[k];
    }
    __syncthreads();
    if (t < 4) {
        float s = 0.f;
#pragma unroll
        for (int ww = 0; ww < 8; ++ww) s += sred[ww][t];
        g_part[bi * 4 + t] = s;
    }
}

// ---------------------------------------------------------------------------
// final: reduce 256x4 partials + fc2
// ---------------------------------------------------------------------------
__global__ void kfc2(const float* __restrict__ fc1b,
                     const float* __restrict__ fc2w,
                     const float* __restrict__ fc2b,
                     float* __restrict__ out) {
    __shared__ float sh[4];
    const int w = threadIdx.x >> 5;   // 128 threads: warp k handles output k
    const int lane = threadIdx.x & 31;
    float s = 0.f;
    for (int i = lane; i < 256; i += 32) s += g_part[i * 4 + w];
#pragma unroll
    for (int o = 16; o; o >>= 1) s += __shfl_xor_sync(0xffffffffu, s, o);
    if (lane == 0) sh[w] = s;
    __syncthreads();
    if (threadIdx.x == 0) {
        float h0 = fmaxf(sh[0] + fc1b[0], 0.f);
        float h1 = fmaxf(sh[1] + fc1b[1], 0.f);
        float h2 = fmaxf(sh[2] + fc1b[2], 0.f);
        float h3 = fmaxf(sh[3] + fc1b[3], 0.f);
        out[0] = fc2w[0] * h0 + fc2w[1] * h1 + fc2w[2] * h2 + fc2w[3] * h3 + fc2b[0];
        out[1] = fc2w[4] * h0 + fc2w[5] * h1 + fc2w[6] * h2 + fc2w[7] * h3 + fc2b[1];
    }
}

// ---------------------------------------------------------------------------
extern "C" void kernel_launch(void* const* d_in, const int* in_sizes, int n_in,
                              void* d_out, int out_size) {
    const float* x    = (const float*)d_in[0];
    const float* w1   = (const float*)d_in[1];
    const float* b1   = (const float*)d_in[2];
    const float* w2   = (const float*)d_in[3];
    const float* b2   = (const float*)d_in[4];
    const float* fc1w = (const float*)d_in[5];
    const float* fc1b = (const float*)d_in[6];
    const float* fc2w = (const float*)d_in[7];
    const float* fc2b = (const float*)d_in[8];

    kprep<<<1, 128>>>(w1, b1, w2, b2);

    void* gp = nullptr;
    cudaGetSymbolAddress(&gp, g_pack);
    cudaMemcpyToSymbolAsync(c_pack, gp, 111 * sizeof(ps_t), 0,
                            cudaMemcpyDeviceToDevice, 0);

    kmain<<<NB / 2, 256>>>(x, fc1w);
    kfc2<<<1, 128>>>(fc1b, fc2w, fc2b, (float*)d_out);
}